// round 11
// baseline (speedup 1.0000x reference)
#include <cuda_runtime.h>
#include <cuda_bf16.h>
#include <cstdint>
#include <cstddef>

#define DINL __device__ __forceinline__

// Problem dims
constexpr int BATCH = 8;
constexpr int CIN   = 256;
constexpr int COUT  = 256;
constexpr int HH = 64, WW = 64;
constexpr int HW = HH * WW;          // 4096
constexpr int KTOT = 9 * CIN;        // 2304
constexpr int KC   = 32;             // channels per K-chunk
constexpr int NCH  = KTOT / KC;      // 72 chunks
constexpr int NSTG = 3;              // pipeline stages (max: 4 stages would need 245KB > 228KB)

// Stage tile layout (bf16, 80B row stride -> conflict-free ldmatrix)
constexpr int ST_AHI = 0;            // 128 rows x 80B = 10240
constexpr int ST_ALO = 10240;
constexpr int ST_BHI = 20480;        // 256 rows x 80B = 20480
constexpr int ST_BLO = 40960;
constexpr int ST_SZ  = 61440;
constexpr int SMEM_BYTES = NSTG * ST_SZ;   // 184320 (also covers 131584B epilogue stage)

// Scratch (device globals; no runtime allocation allowed)
__device__ __align__(16) __nv_bfloat16 g_featHi[BATCH * HW * CIN];  // [b][pix][c]
__device__ __align__(16) __nv_bfloat16 g_featLo[BATCH * HW * CIN];
__device__ __align__(16) __nv_bfloat16 g_wHi[COUT * KTOT];          // [o][k]
__device__ __align__(16) __nv_bfloat16 g_wLo[COUT * KTOT];

// ---------------- prep kernels ----------------
// weights: float4-vectorized hi/lo split (COUT*KTOT = 589824 = 147456 float4)
__global__ void k_wsplit(const float* __restrict__ w) {
    int i = blockIdx.x * blockDim.x + threadIdx.x;
    if (i < COUT * KTOT / 4) {
        float4 v = reinterpret_cast<const float4*>(w)[i];
        __nv_bfloat16 h0 = __float2bfloat16(v.x), h1 = __float2bfloat16(v.y);
        __nv_bfloat16 h2 = __float2bfloat16(v.z), h3 = __float2bfloat16(v.w);
        __nv_bfloat162 hA = __nv_bfloat162(h0, h1), hB = __nv_bfloat162(h2, h3);
        __nv_bfloat162 lA = __nv_bfloat162(__float2bfloat16(v.x - __bfloat162float(h0)),
                                           __float2bfloat16(v.y - __bfloat162float(h1)));
        __nv_bfloat162 lB = __nv_bfloat162(__float2bfloat16(v.z - __bfloat162float(h2)),
                                           __float2bfloat16(v.w - __bfloat162float(h3)));
        reinterpret_cast<__nv_bfloat162*>(g_wHi)[i * 2]     = hA;
        reinterpret_cast<__nv_bfloat162*>(g_wHi)[i * 2 + 1] = hB;
        reinterpret_cast<__nv_bfloat162*>(g_wLo)[i * 2]     = lA;
        reinterpret_cast<__nv_bfloat162*>(g_wLo)[i * 2 + 1] = lB;
    }
}

// feat (B,C,H,W) fp32 -> planar hi/lo channels-last via 32x32 smem transpose
__global__ void k_split_feat(const float* __restrict__ feat) {
    __shared__ float tile[32][33];
    int b  = blockIdx.z;
    int c0 = blockIdx.y * 32;
    int p0 = blockIdx.x * 32;
    int tx = threadIdx.x, ty = threadIdx.y;   // (32, 8)
    const float* src = feat + (size_t)b * CIN * HW;
#pragma unroll
    for (int i = 0; i < 32; i += 8)
        tile[ty + i][tx] = src[(size_t)(c0 + ty + i) * HW + p0 + tx];
    __syncthreads();
#pragma unroll
    for (int i = 0; i < 32; i += 8) {
        float v = tile[tx][ty + i];
        __nv_bfloat16 hi = __float2bfloat16(v);
        __nv_bfloat16 lo = __float2bfloat16(v - __bfloat162float(hi));
        size_t o = ((size_t)b * HW + p0 + ty + i) * CIN + c0 + tx;
        g_featHi[o] = hi; g_featLo[o] = lo;
    }
}

// ---------------- asm helpers ----------------
DINL uint32_t smem_u32(const void* p) {
    uint32_t a;
    asm("{ .reg .u64 t; cvta.to.shared.u64 t, %1; cvt.u32.u64 %0, t; }" : "=r"(a) : "l"(p));
    return a;
}
DINL void cpasync16(uint32_t dst, const void* src) {
    asm volatile("cp.async.cg.shared.global [%0], [%1], 16;" :: "r"(dst), "l"(src));
}
DINL void cp_commit() { asm volatile("cp.async.commit_group;" ::: "memory"); }
DINL void cp_wait1()  { asm volatile("cp.async.wait_group 1;" ::: "memory"); }
DINL void ldsm4(uint32_t r[4], uint32_t addr) {
    asm volatile("ldmatrix.sync.aligned.m8n8.x4.shared.b16 {%0,%1,%2,%3}, [%4];"
                 : "=r"(r[0]), "=r"(r[1]), "=r"(r[2]), "=r"(r[3]) : "r"(addr));
}
DINL void mma16816(float c[4], const uint32_t a[4], uint32_t b0, uint32_t b1) {
    asm volatile("mma.sync.aligned.m16n8k16.row.col.f32.bf16.bf16.f32 "
                 "{%0,%1,%2,%3}, {%4,%5,%6,%7}, {%8,%9}, {%0,%1,%2,%3};"
                 : "+f"(c[0]), "+f"(c[1]), "+f"(c[2]), "+f"(c[3])
                 : "r"(a[0]), "r"(a[1]), "r"(a[2]), "r"(a[3]), "r"(b0), "r"(b1));
}

// ---------------- fused gather-GEMM ----------------
// Grid: 256 CTAs = 8 batches x 32 (pairs of h rows). CTA tile M=128, N=256.
// 512 threads = 16 warps in 4x4; warp tile 32x64. 3-term bf16 fp32-emulation
// (Ahi*Bhi + Ahi*Blo + Alo*Bhi) -> rel_err ~1e-5 vs fp32 reference.
__global__ void __launch_bounds__(512, 1)
k_gemm(const int* __restrict__ scx, const int* __restrict__ scy, float* __restrict__ out) {
    extern __shared__ __align__(128) char smem[];
    uint32_t sb = smem_u32(smem);
    int tid  = threadIdx.x;
    int lane = tid & 31, wid = tid >> 5;
    int wm = wid >> 2, wn = wid & 3;             // 4x4 warp grid
    int b  = blockIdx.x >> 5;
    int h0 = (blockIdx.x & 31) * 2;

    // copy mapping: A 128 rows x 4 x 16B (x2 hi/lo); B 256 rows x 2 x 32B (x2)
    int arow  = tid >> 2, apart = tid & 3;
    int ah = h0 + (arow >> 6), aw = arow & 63;
    int apix0 = ah * WW + aw;
    int brow  = tid >> 1, bhalf = tid & 1;

    // Precompute the 9 gather-row element offsets (loop-invariant): removes the
    // dependent scx/scy gmem load from the per-chunk issue path.
    uint32_t apixoff[9];
    {
        int asamp = apix0 * 8;
        apixoff[0] = (uint32_t)((b * HW + apix0) * CIN + apart * 8);
#pragma unroll
        for (int g = 1; g <= 8; ++g) {
            int si = asamp + g - 1;
            int pix = (__ldg(scy + si) - 1) * WW + (__ldg(scx + si) - 1);
            apixoff[g] = (uint32_t)((b * HW + pix) * CIN + apart * 8);
        }
    }

    // ldmatrix per-lane offsets (within a stage)
    uint32_t a_off = (uint32_t)((wm * 32 + (lane & 15)) * 80 + (lane >> 4) * 16);
    uint32_t b_off = (uint32_t)((wn * 64 + (lane & 7) + (lane >> 4) * 8) * 80
                                + ((lane >> 3) & 1) * 16);

    float acc[2][8][4];
#pragma unroll
    for (int mt = 0; mt < 2; ++mt)
#pragma unroll
        for (int nt = 0; nt < 8; ++nt)
#pragma unroll
            for (int j = 0; j < 4; ++j) acc[mt][nt][j] = 0.0f;

    // ---- issue cp.async copies for chunk s into stage s%NSTG ----
    auto issue = [&](int s) {
        uint32_t stg = sb + (uint32_t)((s % NSTG) * ST_SZ);
        int g  = s >> 3;
        int cb = (s & 7) * 32;
        size_t aoff = (size_t)apixoff[g] + cb;
        uint32_t sa = stg + (uint32_t)(arow * 80 + apart * 16);
        cpasync16(sa + ST_AHI, g_featHi + aoff);
        cpasync16(sa + ST_ALO, g_featLo + aoff);
        size_t boff = (size_t)brow * KTOT + s * 32 + bhalf * 16;
        uint32_t sbb = stg + (uint32_t)(brow * 80 + bhalf * 32);
        cpasync16(sbb + ST_BHI,      g_wHi + boff);
        cpasync16(sbb + ST_BHI + 16, g_wHi + boff + 8);
        cpasync16(sbb + ST_BLO,      g_wLo + boff);
        cpasync16(sbb + ST_BLO + 16, g_wLo + boff + 8);
    };

    // ---- compute one chunk from a stage ----
    auto mma_chunk = [&](uint32_t stg) {
        uint32_t Ahi = stg + ST_AHI + a_off, Alo = stg + ST_ALO + a_off;
        uint32_t Bhi = stg + ST_BHI + b_off, Blo = stg + ST_BLO + b_off;
        uint32_t ahr[2][4], alr[2][4], bb[4][4];
#pragma unroll
        for (int ks = 0; ks < 2; ++ks) {
            uint32_t ko = ks * 32;
            ldsm4(ahr[0], Ahi + ko);
            ldsm4(ahr[1], Ahi + ko + 16 * 80);
#pragma unroll
            for (int bt = 0; bt < 4; ++bt) ldsm4(bb[bt], Bhi + ko + bt * 16 * 80);
#pragma unroll
            for (int mt = 0; mt < 2; ++mt)
#pragma unroll
                for (int nt = 0; nt < 8; ++nt)
                    mma16816(acc[mt][nt], ahr[mt], bb[nt >> 1][(nt & 1) * 2], bb[nt >> 1][(nt & 1) * 2 + 1]);
            ldsm4(alr[0], Alo + ko);
            ldsm4(alr[1], Alo + ko + 16 * 80);
#pragma unroll
            for (int mt = 0; mt < 2; ++mt)
#pragma unroll
                for (int nt = 0; nt < 8; ++nt)
                    mma16816(acc[mt][nt], alr[mt], bb[nt >> 1][(nt & 1) * 2], bb[nt >> 1][(nt & 1) * 2 + 1]);
#pragma unroll
            for (int bt = 0; bt < 4; ++bt) ldsm4(bb[bt], Blo + ko + bt * 16 * 80);
#pragma unroll
            for (int mt = 0; mt < 2; ++mt)
#pragma unroll
                for (int nt = 0; nt < 8; ++nt)
                    mma16816(acc[mt][nt], ahr[mt], bb[nt >> 1][(nt & 1) * 2], bb[nt >> 1][(nt & 1) * 2 + 1]);
        }
    };

    // ---- pipeline: issue-ahead 2, one barrier per chunk ----
    issue(0); cp_commit();
    issue(1); cp_commit();
#pragma unroll 1
    for (int s = 0; s < NCH; ++s) {
        cp_wait1();                 // group s complete (<=1 newest pending)
        __syncthreads();            // stage (s-1)%3 free; stage s visible to all
        if (s + 2 < NCH) issue(s + 2);
        cp_commit();                // unconditional: keeps group count uniform
        mma_chunk(sb + (uint32_t)((s % NSTG) * ST_SZ));
    }
    __syncthreads();

    // ---- epilogue: single pass — stage all 128 m-rows x 256 n (131KB), then
    // fully coalesced stores (lane = w, smem banks (m+n)%32 conflict-free) ----
    float* smf = reinterpret_cast<float*>(smem);
    {
        int r0 = wm * 32;
#pragma unroll
        for (int mt = 0; mt < 2; ++mt)
#pragma unroll
            for (int nt = 0; nt < 8; ++nt) {
                int r = r0 + mt * 16 + (lane >> 2);
                int c = wn * 64 + nt * 8 + (lane & 3) * 2;
                smf[r * 257 + c]           = acc[mt][nt][0];
                smf[r * 257 + c + 1]       = acc[mt][nt][1];
                smf[(r + 8) * 257 + c]     = acc[mt][nt][2];
                smf[(r + 8) * 257 + c + 1] = acc[mt][nt][3];
            }
    }
    __syncthreads();
    {
        int w   = tid & 63;
        int hh  = (tid >> 6) & 1;
        int ns0 = tid >> 7;                       // 4 n-streams of 64
        int m   = hh * 64 + w;
        size_t ob = (size_t)b * COUT * HW + (size_t)(h0 + hh) * WW + w;
#pragma unroll
        for (int i = 0; i < 64; ++i) {
            int n = ns0 * 64 + i;
            out[ob + (size_t)n * HW] = smf[m * 257 + n];
        }
    }
}

// ---------------- launch ----------------
extern "C" void kernel_launch(void* const* d_in, const int* in_sizes, int n_in,
                              void* d_out, int out_size) {
    const float* feat  = (const float*)d_in[0];
    const float* wconv = (const float*)d_in[1];
    const int*   scx   = (const int*)d_in[2];
    const int*   scy   = (const int*)d_in[3];
    float* out = (float*)d_out;

    k_split_feat<<<dim3(HW / 32, CIN / 32, BATCH), dim3(32, 8)>>>(feat);
    k_wsplit<<<(COUT * KTOT / 4 + 255) / 256, 256>>>(wconv);

    cudaFuncSetAttribute(k_gemm, cudaFuncAttributeMaxDynamicSharedMemorySize, SMEM_BYTES);
    k_gemm<<<BATCH * 32, 512, SMEM_BYTES>>>(scx, scy, out);
}